// round 5
// baseline (speedup 1.0000x reference)
#include <cuda_runtime.h>
#include <cuda_fp16.h>
#include <cstdint>

#define CDIM 64
#define KOFF 27
#define MTILE 128
#define THREADS 256
#define NSTAGE 3
#define EPSV 1e-4f
#define NMAXROW 400001

// smem layout (bytes)
#define SM_RED   0                        // 128 floats
#define SM_BIAS  512                      // 64 floats
#define SM_A(b)  (1024 + (b)*16384)       // A: 128 rows x 128B fp16 swizzled
#define SM_B(b)  (50176 + (b)*8192)       // B: 64 rows x 128B fp16 swizzled
#define SMEM_BYTES 74752

__device__ float g_sum[CDIM];
__device__ float g_sq[CDIM];
__device__ float g_scale[CDIM];
__device__ float g_shift[CDIM];
__device__ __align__(16) __half WH[KOFF * 4096];      // [k][n=64][kk=64] swizzled fp16
__device__ __align__(16) __half FH[NMAXROW * CDIM];   // fp16 feature image + zero pad row

__device__ __forceinline__ uint32_t smem_u32(const void* p) {
    uint32_t a;
    asm("{ .reg .u64 t; cvta.to.shared.u64 t, %1; cvt.u32.u64 %0, t; }" : "=r"(a) : "l"(p));
    return a;
}
__device__ __forceinline__ void cp16(uint32_t dst, const void* src) {
    asm volatile("cp.async.cg.shared.global [%0], [%1], 16;"
                 :: "r"(dst), "l"(__cvta_generic_to_global(src)));
}
__device__ __forceinline__ void ldsm4(uint32_t* r, uint32_t addr) {
    asm volatile("ldmatrix.sync.aligned.m8n8.x4.shared.b16 {%0,%1,%2,%3}, [%4];"
                 : "=r"(r[0]), "=r"(r[1]), "=r"(r[2]), "=r"(r[3]) : "r"(addr));
}
__device__ __forceinline__ void mma16816(float* d, const uint32_t* a, const uint32_t* b) {
    asm volatile("mma.sync.aligned.m16n8k16.row.col.f32.f16.f16.f32 "
                 "{%0,%1,%2,%3}, {%4,%5,%6,%7}, {%8,%9}, {%0,%1,%2,%3};"
                 : "+f"(d[0]), "+f"(d[1]), "+f"(d[2]), "+f"(d[3])
                 : "r"(a[0]), "r"(a[1]), "r"(a[2]), "r"(a[3]), "r"(b[0]), "r"(b[1]));
}
__device__ __forceinline__ uint32_t hpack(float a, float b) {
    __half2 t = __floats2half2_rn(a, b);
    return *reinterpret_cast<uint32_t*>(&t);
}
#define CP_COMMIT() asm volatile("cp.async.commit_group;" ::: "memory")
#define CP_WAIT(N)  asm volatile("cp.async.wait_group %0;" :: "n"(N) : "memory")

__global__ void zero_stats_kernel() {
    int t = threadIdx.x;
    if (t < CDIM) { g_sum[t] = 0.0f; g_sq[t] = 0.0f; }
}

// W[k][cin(kk)][cout(nn)] -> WH[k]: row nn (128B = 8 chunks of 8 fp16), chunk = (kk>>3)^(nn&7)
__global__ void wprep_kernel(const float* __restrict__ W) {
    int k = blockIdx.x;
    for (int e = threadIdx.x; e < 4096; e += 256) {
        int nn = e & 63, kk = e >> 6;
        float w = W[k * 4096 + kk * 64 + nn];
        WH[k * 4096 + nn * 64 + (((kk >> 3) ^ (nn & 7)) << 3) + (kk & 7)] = __float2half_rn(w);
    }
}

// feat fp32 [n][64] -> FH fp16 [n+1][64]; row n zeroed
__global__ void fprep_kernel(const float* __restrict__ feat, int n) {
    int i = blockIdx.x * blockDim.x + threadIdx.x;   // one 16B fp16 chunk (8 values)
    const int total = (n + 1) * 8;
    if (i >= total) return;
    uint4 o = make_uint4(0, 0, 0, 0);
    if (i < n * 8) {
        const float4* s = (const float4*)feat + (size_t)i * 2;
        float4 p = s[0], q = s[1];
        o.x = hpack(p.x, p.y); o.y = hpack(p.z, p.w);
        o.z = hpack(q.x, q.y); o.w = hpack(q.z, q.w);
    }
    ((uint4*)FH)[i] = o;
}

__global__ __launch_bounds__(THREADS, 3)
void conv_kernel(const float* __restrict__ bias,
                 const int*   __restrict__ nbr,
                 float* __restrict__ out, int n)
{
    extern __shared__ char smem[];
    const uint32_t sbase = smem_u32(smem);
    float* sred = (float*)(smem + SM_RED);
    float* sb   = (float*)(smem + SM_BIAS);

    const int tid = threadIdx.x;
    const int wid = tid >> 5, lane = tid & 31;
    const int warp_m = wid & 3, warp_n = wid >> 2;
    const int row0 = blockIdx.x * MTILE;

    if (tid < 128) sred[tid] = 0.0f;
    if (tid < CDIM) sb[tid] = bias[tid];

    // fill mapping: 2 threads per row, each covers 4 chunks (32 fp16)
    const int gr = tid >> 1, gh = tid & 1;
    const int rx = gr & 7;
    const int grow = row0 + gr;
    const bool rok = grow < n;
    const int* nrow = nbr + (size_t)(rok ? grow : 0) * KOFF;

    // ldmatrix lane components
    const int r7 = lane & 7;
    const int arow = ((lane >> 3) & 1) * 8 + r7;
    const int asel = lane >> 4;
    const int brow = ((lane >> 4) & 1) * 8 + r7;
    const int bsel = (lane >> 3) & 1;

    float acc[2][4][4];
#pragma unroll
    for (int mt = 0; mt < 2; mt++)
#pragma unroll
        for (int nt = 0; nt < 4; nt++)
#pragma unroll
            for (int j = 0; j < 4; j++) acc[mt][nt][j] = 0.0f;

    auto fill = [&](int k, int buf, int nidx) {
        // B tile: 512 chunks, 2 per thread
        const __half* wsrc = WH + k * 4096;
        const uint32_t bb = sbase + SM_B(buf);
        cp16(bb + tid * 16, wsrc + tid * 8);
        cp16(bb + (tid + 256) * 16, wsrc + (tid + 256) * 8);
        // A tile: row gr, chunks 4*gh..4*gh+3 from FH[nidx]
        const __half* src = FH + (size_t)nidx * CDIM + gh * 32;
        const uint32_t ra = sbase + SM_A(buf) + gr * 128;
#pragma unroll
        for (int t = 0; t < 4; t++)
            cp16(ra + (((4 * gh + t) ^ rx) << 4), src + t * 8);
    };
    auto ldn = [&](int k) -> int { return rok ? nrow[k] : n; };

    // prologue: fill stages 0..NSTAGE-2
#pragma unroll
    for (int s = 0; s < NSTAGE - 1; s++) {
        fill(s, s, ldn(s));
        CP_COMMIT();
    }
    int nidx_cur = ldn(NSTAGE - 1);   // for fill issued at iter 0

    for (int k = 0; k < KOFF; k++) {
        const int buf = k % NSTAGE;
        CP_WAIT(NSTAGE - 2);
        __syncthreads();

        const int kf = k + NSTAGE - 1;
        if (kf < KOFF) fill(kf, kf % NSTAGE, nidx_cur);
        CP_COMMIT();
        if (kf + 1 < KOFF) nidx_cur = ldn(kf + 1);   // prefetch, overlaps MMA

        const uint32_t arow0 = sbase + SM_A(buf) + (warp_m * 32 + arow) * 128;
        const uint32_t arow1 = arow0 + 16 * 128;
        const uint32_t brow0 = sbase + SM_B(buf) + (warp_n * 32 + brow) * 128;
        const uint32_t brow1 = brow0 + 16 * 128;

#pragma unroll
        for (int s = 0; s < 4; s++) {
            const int ach = 2 * s + asel;
            const int bch = 2 * s + bsel;
            uint32_t af[2][4], bf[2][4];
            ldsm4(af[0], arow0 + ((ach ^ r7) << 4));
            ldsm4(af[1], arow1 + ((ach ^ r7) << 4));
            ldsm4(bf[0], brow0 + ((bch ^ r7) << 4));
            ldsm4(bf[1], brow1 + ((bch ^ r7) << 4));
#pragma unroll
            for (int mt = 0; mt < 2; mt++)
#pragma unroll
                for (int nt = 0; nt < 4; nt++)
                    mma16816(acc[mt][nt], af[mt], &bf[nt >> 1][(nt & 1) * 2]);
        }
    }

    // epilogue: bias, store, stats
    const int gid = lane >> 2, tg = lane & 3;
    float s[8], q[8];
#pragma unroll
    for (int j = 0; j < 8; j++) { s[j] = 0.0f; q[j] = 0.0f; }

#pragma unroll
    for (int mt = 0; mt < 2; mt++) {
#pragma unroll
        for (int hf = 0; hf < 2; hf++) {
            const int orow = row0 + warp_m * 32 + mt * 16 + gid + hf * 8;
            const bool ok = orow < n;
            float* op = out + (size_t)orow * CDIM;
#pragma unroll
            for (int nt = 0; nt < 4; nt++) {
                const int col0 = warp_n * 32 + nt * 8 + 2 * tg;
                float x0 = acc[mt][nt][hf * 2 + 0] + sb[col0];
                float x1 = acc[mt][nt][hf * 2 + 1] + sb[col0 + 1];
                if (ok) {
                    *(float2*)(op + col0) = make_float2(x0, x1);
                    s[nt * 2 + 0] += x0;  q[nt * 2 + 0] += x0 * x0;
                    s[nt * 2 + 1] += x1;  q[nt * 2 + 1] += x1 * x1;
                }
            }
        }
    }
#pragma unroll
    for (int j = 0; j < 8; j++) {
#pragma unroll
        for (int off = 4; off < 32; off <<= 1) {
            s[j] += __shfl_xor_sync(0xFFFFFFFFu, s[j], off);
            q[j] += __shfl_xor_sync(0xFFFFFFFFu, q[j], off);
        }
    }
    if (lane < 4) {
#pragma unroll
        for (int j = 0; j < 8; j++) {
            const int col = warp_n * 32 + (j >> 1) * 8 + 2 * lane + (j & 1);
            atomicAdd(&sred[col], s[j]);
            atomicAdd(&sred[64 + col], q[j]);
        }
    }
    __syncthreads();
    if (tid < CDIM)           atomicAdd(&g_sum[tid], sred[tid]);
    else if (tid < 2 * CDIM)  atomicAdd(&g_sq[tid - CDIM], sred[tid]);
}

__global__ void stats_kernel(const float* __restrict__ gamma,
                             const float* __restrict__ beta, float inv_n)
{
    int c = threadIdx.x;
    if (c < CDIM) {
        float m   = g_sum[c] * inv_n;
        float var = g_sq[c] * inv_n - m * m;
        float rs  = rsqrtf(var + EPSV);
        float sc  = gamma[c] * rs;
        g_scale[c] = sc;
        g_shift[c] = beta[c] - sc * m;
    }
}

__global__ void apply_kernel(float* __restrict__ out, int total4)
{
    const float4* sc4 = (const float4*)g_scale;
    const float4* sh4 = (const float4*)g_shift;
    for (int i = blockIdx.x * blockDim.x + threadIdx.x; i < total4;
         i += gridDim.x * blockDim.x) {
        float4 v  = ((float4*)out)[i];
        float4 sc = sc4[i & 15];
        float4 sh = sh4[i & 15];
        float y0 = v.x * sc.x + sh.x;
        float y1 = v.y * sc.y + sh.y;
        float y2 = v.z * sc.z + sh.z;
        float y3 = v.w * sc.w + sh.w;
        const float L = 1.0f / 3.0f;
        v.x = y0 > 0.f ? y0 : y0 * L;
        v.y = y1 > 0.f ? y1 : y1 * L;
        v.z = y2 > 0.f ? y2 : y2 * L;
        v.w = y3 > 0.f ? y3 : y3 * L;
        ((float4*)out)[i] = v;
    }
}

extern "C" void kernel_launch(void* const* d_in, const int* in_sizes, int n_in,
                              void* d_out, int out_size)
{
    const float* feat  = (const float*)d_in[0];
    const float* W     = (const float*)d_in[1];
    const float* bias  = (const float*)d_in[2];
    const float* gamma = (const float*)d_in[3];
    const float* beta  = (const float*)d_in[4];
    const int*   nbr   = (const int*)d_in[5];
    const int n = in_sizes[0] / CDIM;

    cudaFuncSetAttribute(conv_kernel,
                         cudaFuncAttributeMaxDynamicSharedMemorySize, SMEM_BYTES);

    zero_stats_kernel<<<1, 128>>>();
    wprep_kernel<<<KOFF, 256>>>(W);
    fprep_kernel<<<((n + 1) * 8 + 255) / 256, 256>>>(feat, n);
    conv_kernel<<<(n + MTILE - 1) / MTILE, THREADS, SMEM_BYTES>>>(
        bias, nbr, (float*)d_out, n);
    stats_kernel<<<1, CDIM>>>(gamma, beta, 1.0f / (float)n);
    apply_kernel<<<2048, 256>>>((float*)d_out, n * (CDIM / 4));
}